// round 8
// baseline (speedup 1.0000x reference)
#include <cuda_runtime.h>
#include <cuda_bf16.h>
#include <stdint.h>
#include <math.h>

#define NB   64
#define LSEQ 510
#define DDIM 768
#define L1   128
#define KN   20
#define OUTD 300
#define EPSV 1e-5f

#define NSPAN1 (NB * L1)          // 8192
#define NSPANK (NB * KN)          // 1280
#define NSPANS (NSPAN1 + NSPANK)  // 9472
#define TROWS  64
#define NTILES (NSPANS / TROWS)   // 148 == #SMs
#define NBLK1T (NSPAN1 / TROWS)   // 128

#define NCHUNK 12                 // K chunks of 64
#define NPADB  320

#define H1_OFF    0
#define SCORE_OFF (NB * L1 * OUTD)
#define HK_OFF    (2 * NB * L1 * OUTD)
#define SK_OFF    (HK_OFF + NB * KN * OUTD)

#define B_CHUNK_BYTES 40960        // 320 rows x 128B

__device__ __align__(16) unsigned char g_Bhi[NCHUNK * B_CHUNK_BYTES];
__device__ __align__(16) unsigned char g_Blo[NCHUNK * B_CHUNK_BYTES];
__device__ float g_scores[NSPANS];
__device__ int   g_mask_mode;
__device__ int   g_bar;            // monotone grid barrier counter (replay-safe)

// smem layout (dynamic): per stage Ahi 8K | Alo 8K | Bhi 40K | Blo 40K
#define STAGE_BYTES 98304
#define OFF_AHI 0
#define OFF_ALO 8192
#define OFF_BHI 16384
#define OFF_BLO 57344
#define SM_TAB  (2 * STAGE_BYTES)
#define SM_RED  (SM_TAB + 5120)
#define SMEM_BYTES (SM_RED + 3584)

static __device__ __forceinline__ uint32_t smem_u32(const void* p) {
    uint32_t a;
    asm("{ .reg .u64 t; cvta.to.shared.u64 t, %1; cvt.u32.u64 %0, t; }" : "=r"(a) : "l"(p));
    return a;
}
static __device__ __forceinline__ void cp16(uint32_t s, const void* g) {
    asm volatile("cp.async.cg.shared.global [%0], [%1], 16;" :: "r"(s), "l"(g) : "memory");
}
static __device__ __forceinline__ void ldsm4(uint32_t* r, uint32_t addr) {
    asm volatile("ldmatrix.sync.aligned.m8n8.x4.shared.b16 {%0,%1,%2,%3}, [%4];"
                 : "=r"(r[0]), "=r"(r[1]), "=r"(r[2]), "=r"(r[3]) : "r"(addr));
}
static __device__ __forceinline__ void ldsm2(uint32_t* r, uint32_t addr) {
    asm volatile("ldmatrix.sync.aligned.m8n8.x2.shared.b16 {%0,%1}, [%2];"
                 : "=r"(r[0]), "=r"(r[1]) : "r"(addr));
}
static __device__ __forceinline__ void mma16816(float* c, const uint32_t* a,
                                                const uint32_t* b) {
    asm volatile(
        "mma.sync.aligned.m16n8k16.row.col.f32.bf16.bf16.f32 "
        "{%0,%1,%2,%3}, {%4,%5,%6,%7}, {%8,%9}, {%0,%1,%2,%3};"
        : "+f"(c[0]), "+f"(c[1]), "+f"(c[2]), "+f"(c[3])
        : "r"(a[0]), "r"(a[1]), "r"(a[2]), "r"(a[3]), "r"(b[0]), "r"(b[1]));
}
static __device__ __forceinline__ uint32_t swz_addr(uint32_t base, int row, int u) {
    return base + row * 128 + ((u ^ (row & 7)) << 4);
}
static __device__ __forceinline__ void split_store16(const float* v, float inv,
                                                     unsigned char* dhi,
                                                     unsigned char* dlo) {
    union { unsigned short u[8]; uint4 q; } ph, pl;
    #pragma unroll
    for (int j = 0; j < 8; j++) {
        float x = v[j] * inv;
        __nv_bfloat16 h = __float2bfloat16(x);
        __nv_bfloat16 l = __float2bfloat16(x - __bfloat162float(h));
        ph.u[j] = *(unsigned short*)&h;
        pl.u[j] = *(unsigned short*)&l;
    }
    *(uint4*)dhi = ph.q;
    *(uint4*)dlo = pl.q;
}
static __device__ __forceinline__ bool read_mask(const void* m, int i, int mode) {
    if (mode == 0) return ((const unsigned char*)m)[i] != 0;
    if (mode == 1) return ((const int*)m)[i] != 0;
    return ((const float*)m)[i] != 0.0f;
}

// ---------------------------------------------------------------------------
// prep_small: blocks [0,120): W convert; block 120: mask detect.
// ---------------------------------------------------------------------------
__global__ __launch_bounds__(256)
void prep_small_kernel(const float* __restrict__ W,
                       const unsigned char* __restrict__ mask1,
                       const unsigned char* __restrict__ maskk) {
    const int bid = blockIdx.x;
    const int t = threadIdx.x;
    if (bid < 120) {
        const int u = bid * 256 + t;                // [0, 30720)
        const int row = u / 96;
        const int idx8 = u - row * 96;
        const int c0 = idx8 * 8;
        float v[8];
        if (row < OUTD) {
            const float4* p4 = (const float4*)(W + (size_t)row * DDIM + c0);
            float4 a = p4[0], bb = p4[1];
            v[0] = a.x; v[1] = a.y; v[2] = a.z; v[3] = a.w;
            v[4] = bb.x; v[5] = bb.y; v[6] = bb.z; v[7] = bb.w;
        } else {
            #pragma unroll
            for (int j = 0; j < 8; j++) v[j] = 0.0f;
        }
        const int chunk = idx8 >> 3, grp = idx8 & 7;
        size_t off = (size_t)chunk * B_CHUNK_BYTES + row * 128 + grp * 16;
        split_store16(v, 1.0f, g_Bhi + off, g_Blo + off);
    } else {
        __shared__ int f_weird, f_odd;
        if (t == 0) { f_weird = 0; f_odd = 0; }
        __syncthreads();
        int lw = 0, lo = 0;
        for (int i = t; i < NB * KN; i += 256) {
            unsigned char vv = maskk[i];
            if (vv > 1) lw = 1;
            if (vv && (i & 3)) lo = 1;
        }
        for (int i = t; i < NB * L1; i += 256) {
            unsigned char vv = mask1[i];
            if (vv > 1) lw = 1;
            if (vv && (i & 3)) lo = 1;
        }
        if (lw) atomicOr(&f_weird, 1);
        if (lo) atomicOr(&f_odd, 1);
        __syncthreads();
        if (t == 0) g_mask_mode = f_weird ? 2 : (f_odd ? 0 : 1);
    }
}

// ---------------------------------------------------------------------------
// mega: fused span-pool + bf16-split mma.sync GEMM + LN + score + grid barrier
//       + masked softmax + broadcast. 148 CTAs x 256 threads (one full wave).
// ---------------------------------------------------------------------------
__global__ __launch_bounds__(256, 1)
void mega_kernel(const float* __restrict__ t1, const float* __restrict__ know,
                 const int* __restrict__ s1s, const int* __restrict__ s1e,
                 const int* __restrict__ sks, const int* __restrict__ ske,
                 const float* __restrict__ b_lin, const float* __restrict__ gamma,
                 const float* __restrict__ beta, const float* __restrict__ w_score,
                 const float* __restrict__ b_score,
                 const void* __restrict__ mask1, const void* __restrict__ maskk,
                 float* __restrict__ out) {
    extern __shared__ char smem[];
    const uint32_t sbase = smem_u32(smem);
    const int t = threadIdx.x;
    const int blk = blockIdx.x;
    const int w = t >> 5, lane = t & 31;
    const int wm = w >> 2, wn = w & 3;
    const int rm0 = wm * 32, nb0 = wn * 80;

    // ---- parameter tables ----
    float* tb = (float*)(smem + SM_TAB);
    for (int i = t; i < NPADB; i += 256) {
        tb[i]             = (i < OUTD) ? b_lin[i]   : 0.0f;
        tb[NPADB + i]     = (i < OUTD) ? gamma[i]   : 0.0f;
        tb[2 * NPADB + i] = (i < OUTD) ? beta[i]    : 0.0f;
        tb[3 * NPADB + i] = (i < OUTD) ? w_score[i] : 0.0f;
    }

    // ---- per-thread span metadata: thread handles row r, col-quad q ----
    const int r = t >> 2, q = t & 3;
    const int rid = blk * TROWS + r;
    const float* rp[4];
    float wt[4];
    {
        const float* src; int b, s, e;
        if (rid < NSPAN1) { src = t1; b = rid >> 7; s = s1s[rid]; e = s1e[rid]; }
        else { int j = rid - NSPAN1; src = know; b = j / KN; s = sks[j]; e = ske[j]; }
        int len = e - s; if (len < 1) len = 1;
        const float inv = 1.0f / (float)len;
        const float* base = src + (size_t)(b * LSEQ + s) * DDIM;
        #pragma unroll
        for (int rr = 0; rr < 4; rr++) {
            int cr = rr < len ? rr : len - 1;
            rp[rr] = base + (size_t)cr * DDIM;
            wt[rr] = (rr < len) ? inv : 0.0f;
        }
    }

    float acc[2][10][4];
    #pragma unroll
    for (int mf = 0; mf < 2; mf++)
        #pragma unroll
        for (int nf = 0; nf < 10; nf++)
            #pragma unroll
            for (int qq = 0; qq < 4; qq++) acc[mf][nf][qq] = 0.0f;

    // ---- pool chunk 0 into regs ----
    float v[16];
    {
        const int c0 = q * 16;
        #pragma unroll
        for (int j = 0; j < 16; j++) v[j] = 0.0f;
        #pragma unroll
        for (int rr = 0; rr < 4; rr++) {
            #pragma unroll
            for (int j4 = 0; j4 < 4; j4++) {
                float4 f = *(const float4*)(rp[rr] + c0 + j4 * 4);
                v[j4 * 4 + 0] += wt[rr] * f.x;
                v[j4 * 4 + 1] += wt[rr] * f.y;
                v[j4 * 4 + 2] += wt[rr] * f.z;
                v[j4 * 4 + 3] += wt[rr] * f.w;
            }
        }
    }
    // ---- issue B chunk 0 ----
    {
        const uint32_t sb = sbase;
        #pragma unroll
        for (int j = 0; j < 10; j++) {
            int idx = t + 256 * j;
            int row = idx >> 3, u = idx & 7;
            uint32_t d = row * 128 + ((u ^ (row & 7)) << 4);
            cp16(sb + OFF_BHI + d, g_Bhi + idx * 16);
            cp16(sb + OFF_BLO + d, g_Blo + idx * 16);
        }
        asm volatile("cp.async.commit_group;" ::: "memory");
    }

    #pragma unroll 1
    for (int c = 0; c < NCHUNK; ++c) {
        const uint32_t sb = sbase + (c & 1) * STAGE_BYTES;
        // store pooled A(c) (split hi/lo) into this stage
        {
            union { unsigned short u[8]; uint4 qd; } ph, pl;
            #pragma unroll
            for (int h = 0; h < 2; h++) {
                #pragma unroll
                for (int j = 0; j < 8; j++) {
                    float x = v[h * 8 + j];
                    __nv_bfloat16 hi = __float2bfloat16(x);
                    __nv_bfloat16 lo = __float2bfloat16(x - __bfloat162float(hi));
                    ph.u[j] = *(unsigned short*)&hi;
                    pl.u[j] = *(unsigned short*)&lo;
                }
                int u = 2 * q + h;
                uint32_t d = r * 128 + ((u ^ (r & 7)) << 4);
                *(uint4*)(smem + (c & 1) * STAGE_BYTES + OFF_AHI + d) = ph.qd;
                *(uint4*)(smem + (c & 1) * STAGE_BYTES + OFF_ALO + d) = pl.qd;
            }
        }
        if (c + 1 < NCHUNK) {
            const uint32_t sb2 = sbase + ((c + 1) & 1) * STAGE_BYTES;
            const unsigned char* bh = g_Bhi + (size_t)(c + 1) * B_CHUNK_BYTES;
            const unsigned char* bl = g_Blo + (size_t)(c + 1) * B_CHUNK_BYTES;
            #pragma unroll
            for (int j = 0; j < 10; j++) {
                int idx = t + 256 * j;
                int row = idx >> 3, u = idx & 7;
                uint32_t d = row * 128 + ((u ^ (row & 7)) << 4);
                cp16(sb2 + OFF_BHI + d, bh + idx * 16);
                cp16(sb2 + OFF_BLO + d, bl + idx * 16);
            }
            asm volatile("cp.async.commit_group;" ::: "memory");
            asm volatile("cp.async.wait_group 1;" ::: "memory");
        } else {
            asm volatile("cp.async.wait_group 0;" ::: "memory");
        }
        __syncthreads();

        // MMA(c)
        {
            const int sub = lane >> 3, rin = lane & 7;
            #pragma unroll
            for (int ks = 0; ks < 4; ks++) {
                uint32_t ah[2][4], al[2][4];
                #pragma unroll
                for (int mf = 0; mf < 2; mf++) {
                    int row = rm0 + mf * 16 + rin + ((sub & 1) << 3);
                    int u = ks * 2 + (sub >> 1);
                    ldsm4(ah[mf], swz_addr(sb + OFF_AHI, row, u));
                    ldsm4(al[mf], swz_addr(sb + OFF_ALO, row, u));
                }
                #pragma unroll
                for (int nf = 0; nf < 10; nf++) {
                    int brow = nb0 + nf * 8 + rin;
                    int bu = ks * 2 + (sub & 1);
                    uint32_t bh[2], bl[2];
                    ldsm2(bh, swz_addr(sb + OFF_BHI, brow, bu));
                    mma16816(acc[0][nf], ah[0], bh);
                    mma16816(acc[1][nf], ah[1], bh);
                    mma16816(acc[0][nf], al[0], bh);
                    mma16816(acc[1][nf], al[1], bh);
                    ldsm2(bl, swz_addr(sb + OFF_BLO, brow, bu));
                    mma16816(acc[0][nf], ah[0], bl);
                    mma16816(acc[1][nf], ah[1], bl);
                }
            }
        }
        // pool chunk c+1 (overlaps tail of other warps' MMA)
        if (c + 1 < NCHUNK) {
            const int c0 = (c + 1) * 64 + q * 16;
            #pragma unroll
            for (int j = 0; j < 16; j++) v[j] = 0.0f;
            #pragma unroll
            for (int rr = 0; rr < 4; rr++) {
                #pragma unroll
                for (int j4 = 0; j4 < 4; j4++) {
                    float4 f = *(const float4*)(rp[rr] + c0 + j4 * 4);
                    v[j4 * 4 + 0] += wt[rr] * f.x;
                    v[j4 * 4 + 1] += wt[rr] * f.y;
                    v[j4 * 4 + 2] += wt[rr] * f.z;
                    v[j4 * 4 + 3] += wt[rr] * f.w;
                }
            }
        }
        __syncthreads();
    }

    // ---- epilogue: bias + LayerNorm + h write + score ----
    float* red_sum  = (float*)(smem + SM_RED);
    float* red_sq   = red_sum + 256;
    float* red_sc   = red_sum + 512;
    float* red_mean = red_sum + 768;
    float* red_rstd = red_sum + 832;

    float sum[4] = {0, 0, 0, 0}, sq[4] = {0, 0, 0, 0};
    #pragma unroll
    for (int mf = 0; mf < 2; mf++)
        #pragma unroll
        for (int nf = 0; nf < 10; nf++) {
            int c0 = nb0 + nf * 8 + 2 * (lane & 3);
            float v0 = acc[mf][nf][0] + tb[c0];
            float v1 = acc[mf][nf][1] + tb[c0 + 1];
            float v2 = acc[mf][nf][2] + tb[c0];
            float v3 = acc[mf][nf][3] + tb[c0 + 1];
            sum[mf * 2]     += v0 + v1;  sq[mf * 2]     += v0 * v0 + v1 * v1;
            sum[mf * 2 + 1] += v2 + v3;  sq[mf * 2 + 1] += v2 * v2 + v3 * v3;
        }
    #pragma unroll
    for (int ri = 0; ri < 4; ri++) {
        #pragma unroll
        for (int o = 1; o <= 2; o <<= 1) {
            sum[ri] += __shfl_xor_sync(0xffffffffu, sum[ri], o);
            sq[ri]  += __shfl_xor_sync(0xffffffffu, sq[ri], o);
        }
    }
    if ((lane & 3) == 0) {
        #pragma unroll
        for (int ri = 0; ri < 4; ri++) {
            int row = rm0 + (ri >> 1) * 16 + (ri & 1) * 8 + (lane >> 2);
            red_sum[wn * 64 + row] = sum[ri];
            red_sq[wn * 64 + row]  = sq[ri];
        }
    }
    __syncthreads();
    if (t < TROWS) {
        float s = red_sum[t] + red_sum[64 + t] + red_sum[128 + t] + red_sum[192 + t];
        float qv = red_sq[t] + red_sq[64 + t] + red_sq[128 + t] + red_sq[192 + t];
        float mean = s * (1.0f / OUTD);
        float var = qv * (1.0f / OUTD) - mean * mean;
        red_mean[t] = mean;
        red_rstd[t] = rsqrtf(fmaxf(var, 0.0f) + EPSV);
    }
    __syncthreads();

    const float* sg  = tb + NPADB;
    const float* sbe = tb + 2 * NPADB;
    const float* sw  = tb + 3 * NPADB;
    float sc[4] = {0, 0, 0, 0};
    #pragma unroll
    for (int mf = 0; mf < 2; mf++) {
        int row01 = rm0 + mf * 16 + (lane >> 2);
        int row23 = row01 + 8;
        float m0 = red_mean[row01], r0 = red_rstd[row01];
        float m1 = red_mean[row23], r1 = red_rstd[row23];
        int g01 = blk * TROWS + row01;
        int g23 = blk * TROWS + row23;
        float* o01 = (blk < NBLK1T) ? out + (size_t)g01 * OUTD
                                    : out + HK_OFF + (size_t)(g01 - NSPAN1) * OUTD;
        float* o23 = (blk < NBLK1T) ? out + (size_t)g23 * OUTD
                                    : out + HK_OFF + (size_t)(g23 - NSPAN1) * OUTD;
        #pragma unroll
        for (int nf = 0; nf < 10; nf++) {
            int c0 = nb0 + nf * 8 + 2 * (lane & 3);
            float v0 = acc[mf][nf][0] + tb[c0];
            float v1 = acc[mf][nf][1] + tb[c0 + 1];
            float v2 = acc[mf][nf][2] + tb[c0];
            float v3 = acc[mf][nf][3] + tb[c0 + 1];
            float h0 = (v0 - m0) * r0 * sg[c0]     + sbe[c0];
            float h1 = (v1 - m0) * r0 * sg[c0 + 1] + sbe[c0 + 1];
            float h2 = (v2 - m1) * r1 * sg[c0]     + sbe[c0];
            float h3 = (v3 - m1) * r1 * sg[c0 + 1] + sbe[c0 + 1];
            sc[mf * 2]     += h0 * sw[c0] + h1 * sw[c0 + 1];
            sc[mf * 2 + 1] += h2 * sw[c0] + h3 * sw[c0 + 1];
            if (c0 < OUTD) {
                *(float2*)(o01 + c0) = make_float2(h0, h1);
                *(float2*)(o23 + c0) = make_float2(h2, h3);
            }
        }
    }
    #pragma unroll
    for (int ri = 0; ri < 4; ri++)
        #pragma unroll
        for (int o = 1; o <= 2; o <<= 1)
            sc[ri] += __shfl_xor_sync(0xffffffffu, sc[ri], o);
    if ((lane & 3) == 0) {
        #pragma unroll
        for (int ri = 0; ri < 4; ri++) {
            int row = rm0 + (ri >> 1) * 16 + (ri & 1) * 8 + (lane >> 2);
            red_sc[wn * 64 + row] = sc[ri];
        }
    }
    __syncthreads();
    if (t < TROWS) {
        g_scores[blk * TROWS + t] =
            red_sc[t] + red_sc[64 + t] + red_sc[128 + t] + red_sc[192 + t] + b_score[0];
    }

    // ---- grid barrier (all 148 CTAs resident: 1 wave) ----
    __threadfence();
    __syncthreads();
    if (t == 0) {
        int my = atomicAdd(&g_bar, 1) + 1;
        int target = ((my + NTILES - 1) / NTILES) * NTILES;
        while (atomicAdd(&g_bar, 0) < target) { }
        __threadfence();
    }
    __syncthreads();

    // ---- softmax + broadcast phase ----
    const int mode = g_mask_mode;
    if (blk < NB) {
        const int b = blk;
        float* sh = (float*)smem;          // probs [128], red at [128..131]
        float* red = sh + 128;
        float scv = 0.0f; bool msk = true;
        if (t < L1) {
            scv = *((volatile float*)&g_scores[b * L1 + t]);
            msk = read_mask(mask1, b * L1 + t, mode);
        }
        float val = (t < L1 && !msk) ? scv : -3.0e38f;
        float mx = val;
        #pragma unroll
        for (int o = 16; o; o >>= 1) mx = fmaxf(mx, __shfl_xor_sync(0xffffffffu, mx, o));
        if (t < L1 && (t & 31) == 0) red[t >> 5] = mx;
        __syncthreads();
        mx = fmaxf(fmaxf(red[0], red[1]), fmaxf(red[2], red[3]));
        __syncthreads();
        float ex = (t < L1 && !msk) ? expf(scv - mx) : 0.0f;
        float sm = ex;
        #pragma unroll
        for (int o = 16; o; o >>= 1) sm += __shfl_xor_sync(0xffffffffu, sm, o);
        if (t < L1 && (t & 31) == 0) red[t >> 5] = sm;
        __syncthreads();
        sm = red[0] + red[1] + red[2] + red[3];
        if (t < L1) sh[t] = ex / sm;
        __syncthreads();
        float4* o4 = (float4*)(out + SCORE_OFF + (size_t)b * L1 * OUTD);
        const int Q = OUTD / 4;            // 75
        for (int w2 = t; w2 < L1 * Q; w2 += 256) {
            int row = w2 / Q;
            float p = sh[row];
            o4[w2] = make_float4(p, p, p, p);
        }
    } else if (blk < 2 * NB) {
        const int b = blk - NB;
        if (t < 32) {
            bool msk = true;
            float scv = 0.0f;
            if (t < KN) {
                msk = read_mask(maskk, b * KN + t, mode);
                scv = *((volatile float*)&g_scores[NSPAN1 + b * KN + t]);
            }
            float val = (t < KN && !msk) ? scv : -3.0e38f;
            float mx = val;
            #pragma unroll
            for (int o = 16; o; o >>= 1) mx = fmaxf(mx, __shfl_xor_sync(0xffffffffu, mx, o));
            float ex = (t < KN && !msk) ? expf(scv - mx) : 0.0f;
            float sm = ex;
            #pragma unroll
            for (int o = 16; o; o >>= 1) sm += __shfl_xor_sync(0xffffffffu, sm, o);
            if (t < KN) out[SK_OFF + b * KN + t] = ex / sm;
        }
    }
}

extern "C" void kernel_launch(void* const* d_in, const int* in_sizes, int n_in,
                              void* d_out, int out_size) {
    const float* t1    = (const float*)d_in[0];
    const float* know  = (const float*)d_in[1];
    const int*   s1s   = (const int*)d_in[2];
    const int*   s1e   = (const int*)d_in[3];
    const void*  mask1 = d_in[4];
    const int*   sks   = (const int*)d_in[5];
    const int*   ske   = (const int*)d_in[6];
    const void*  maskk = d_in[7];
    const float* W     = (const float*)d_in[8];
    const float* bl    = (const float*)d_in[9];
    const float* gm    = (const float*)d_in[10];
    const float* bt    = (const float*)d_in[11];
    const float* ws    = (const float*)d_in[12];
    const float* bs    = (const float*)d_in[13];
    float* out = (float*)d_out;

    cudaFuncSetAttribute(mega_kernel, cudaFuncAttributeMaxDynamicSharedMemorySize,
                         SMEM_BYTES);
    prep_small_kernel<<<121, 256>>>(W, (const unsigned char*)mask1,
                                    (const unsigned char*)maskk);
    mega_kernel<<<NTILES, 256, SMEM_BYTES>>>(t1, know, s1s, s1e, sks, ske,
                                             bl, gm, bt, ws, bs,
                                             mask1, maskk, out);
}

// round 9
// speedup vs baseline: 1.1482x; 1.1482x over previous
#include <cuda_runtime.h>
#include <cuda_fp16.h>
#include <stdint.h>
#include <math.h>

#define NB   64
#define LSEQ 510
#define DDIM 768
#define L1   128
#define KN   20
#define OUTD 300
#define EPSV 1e-5f

#define NSPAN1 (NB * L1)          // 8192
#define NSPANK (NB * KN)          // 1280
#define NSPANS (NSPAN1 + NSPANK)  // 9472
#define TROWS  32
#define NTILES (NSPANS / TROWS)   // 296 = 2 CTAs x 148 SMs
#define NBLK1T (NSPAN1 / TROWS)   // 256

#define NCHUNK 12                 // K chunks of 64
#define NPADB  320

#define H1_OFF    0
#define SCORE_OFF (NB * L1 * OUTD)
#define HK_OFF    (2 * NB * L1 * OUTD)
#define SK_OFF    (HK_OFF + NB * KN * OUTD)

#define A_CHUNK_BYTES 4096         // 32 rows x 128B (fp16)
#define B_CHUNK_BYTES 40960        // 320 rows x 128B (fp16)

__device__ __align__(16) unsigned char g_Ahi[NTILES * NCHUNK * A_CHUNK_BYTES];
__device__ __align__(16) unsigned char g_Alo[NTILES * NCHUNK * A_CHUNK_BYTES];
__device__ __align__(16) unsigned char g_Bhi[NCHUNK * B_CHUNK_BYTES];
__device__ float g_scores[NSPANS];
__device__ int   g_mask_mode;

// smem: per stage Ahi 4K | Alo 4K | Bhi 40K = 48K; x2 stages; tables; reduction
#define STAGE_BYTES 49152
#define OFF_AHI 0
#define OFF_ALO 4096
#define OFF_BHI 8192
#define SM_TAB  (2 * STAGE_BYTES)          // 98304
#define SM_RED  (SM_TAB + 5120)           // 103424
#define SMEM_BYTES (SM_RED + 3584)        // 107008 -> 2 CTAs/SM

static __device__ __forceinline__ uint32_t smem_u32(const void* p) {
    uint32_t a;
    asm("{ .reg .u64 t; cvta.to.shared.u64 t, %1; cvt.u32.u64 %0, t; }" : "=r"(a) : "l"(p));
    return a;
}
static __device__ __forceinline__ void cp16(uint32_t s, const void* g) {
    asm volatile("cp.async.cg.shared.global [%0], [%1], 16;" :: "r"(s), "l"(g) : "memory");
}
static __device__ __forceinline__ void ldsm4(uint32_t* r, uint32_t addr) {
    asm volatile("ldmatrix.sync.aligned.m8n8.x4.shared.b16 {%0,%1,%2,%3}, [%4];"
                 : "=r"(r[0]), "=r"(r[1]), "=r"(r[2]), "=r"(r[3]) : "r"(addr));
}
static __device__ __forceinline__ void ldsm2(uint32_t* r, uint32_t addr) {
    asm volatile("ldmatrix.sync.aligned.m8n8.x2.shared.b16 {%0,%1}, [%2];"
                 : "=r"(r[0]), "=r"(r[1]) : "r"(addr));
}
static __device__ __forceinline__ void mma16816(float* c, const uint32_t* a,
                                                const uint32_t* b) {
    asm volatile(
        "mma.sync.aligned.m16n8k16.row.col.f32.f16.f16.f32 "
        "{%0,%1,%2,%3}, {%4,%5,%6,%7}, {%8,%9}, {%0,%1,%2,%3};"
        : "+f"(c[0]), "+f"(c[1]), "+f"(c[2]), "+f"(c[3])
        : "r"(a[0]), "r"(a[1]), "r"(a[2]), "r"(a[3]), "r"(b[0]), "r"(b[1]));
}
static __device__ __forceinline__ uint32_t swz_addr(uint32_t base, int row, int u) {
    return base + row * 128 + ((u ^ (row & 7)) << 4);
}
static __device__ __forceinline__ bool read_mask(const void* m, int i, int mode) {
    if (mode == 0) return ((const unsigned char*)m)[i] != 0;
    if (mode == 1) return ((const int*)m)[i] != 0;
    return ((const float*)m)[i] != 0.0f;
}

// ---------------------------------------------------------------------------
// prep: blocks [0,1184): warp-per-span pool + fp16 hi/lo split;
//       blocks [1184,1304): W -> fp16 hi; block 1304: mask detect.
// ---------------------------------------------------------------------------
#define PREP_SPAN_BLKS (NSPANS / 8)   // 1184
#define PREP_W_BLKS    120
#define PREP_BLKS      (PREP_SPAN_BLKS + PREP_W_BLKS + 1)

__global__ __launch_bounds__(256)
void prep_kernel(const float* __restrict__ t1, const float* __restrict__ know,
                 const int* __restrict__ s1s, const int* __restrict__ s1e,
                 const int* __restrict__ sks, const int* __restrict__ ske,
                 const float* __restrict__ W,
                 const unsigned char* __restrict__ mask1,
                 const unsigned char* __restrict__ maskk) {
    const int bid = blockIdx.x;
    const int t = threadIdx.x;
    if (bid < PREP_SPAN_BLKS) {
        const int w = t >> 5, lane = t & 31;
        const int rid = bid * 8 + w;
        const float* src; int b, s, e;
        if (rid < NSPAN1) { src = t1; b = rid >> 7; s = s1s[rid]; e = s1e[rid]; }
        else { int j = rid - NSPAN1; src = know; b = j / KN; s = sks[j]; e = ske[j]; }
        int len = e - s; if (len < 1) len = 1;
        const float inv = 1.0f / (float)len;
        const float* base = src + (size_t)(b * LSEQ + s) * DDIM;
        const int tile = rid >> 5, r = rid & 31;
        #pragma unroll
        for (int g = 0; g < 3; g++) {
            const int idx8 = g * 32 + lane;     // 0..95
            const int c0 = idx8 * 8;
            float v[8];
            #pragma unroll
            for (int j = 0; j < 8; j++) v[j] = 0.0f;
            for (int rr = 0; rr < len; rr++) {
                const float4* p4 = (const float4*)(base + (size_t)rr * DDIM + c0);
                float4 a = p4[0], bb = p4[1];
                v[0] += a.x; v[1] += a.y; v[2] += a.z; v[3] += a.w;
                v[4] += bb.x; v[5] += bb.y; v[6] += bb.z; v[7] += bb.w;
            }
            union { unsigned short u[8]; uint4 q; } ph, pl;
            #pragma unroll
            for (int j = 0; j < 8; j++) {
                float x = v[j] * inv;
                __half h = __float2half_rn(x);
                __half l = __float2half_rn(x - __half2float(h));
                ph.u[j] = *(unsigned short*)&h;
                pl.u[j] = *(unsigned short*)&l;
            }
            const int chunk = idx8 >> 3, grp = idx8 & 7;
            size_t off = (size_t)(tile * NCHUNK + chunk) * A_CHUNK_BYTES
                       + r * 128 + grp * 16;
            *(uint4*)(g_Ahi + off) = ph.q;
            *(uint4*)(g_Alo + off) = pl.q;
        }
    } else if (bid < PREP_SPAN_BLKS + PREP_W_BLKS) {
        const int u = (bid - PREP_SPAN_BLKS) * 256 + t;   // [0, 30720)
        const int row = u / 96;
        const int idx8 = u - row * 96;
        const int c0 = idx8 * 8;
        union { unsigned short s[8]; uint4 q; } ph;
        if (row < OUTD) {
            const float4* p4 = (const float4*)(W + (size_t)row * DDIM + c0);
            float4 a = p4[0], bb = p4[1];
            float v[8] = {a.x, a.y, a.z, a.w, bb.x, bb.y, bb.z, bb.w};
            #pragma unroll
            for (int j = 0; j < 8; j++) {
                __half h = __float2half_rn(v[j]);
                ph.s[j] = *(unsigned short*)&h;
            }
        } else {
            ph.q = make_uint4(0, 0, 0, 0);
        }
        const int chunk = idx8 >> 3, grp = idx8 & 7;
        size_t off = (size_t)chunk * B_CHUNK_BYTES + row * 128 + grp * 16;
        *(uint4*)(g_Bhi + off) = ph.q;
    } else {
        __shared__ int f_weird, f_odd;
        if (t == 0) { f_weird = 0; f_odd = 0; }
        __syncthreads();
        int lw = 0, lo = 0;
        for (int i = t; i < NB * KN; i += 256) {
            unsigned char vv = maskk[i];
            if (vv > 1) lw = 1;
            if (vv && (i & 3)) lo = 1;
        }
        for (int i = t; i < NB * L1; i += 256) {
            unsigned char vv = mask1[i];
            if (vv > 1) lw = 1;
            if (vv && (i & 3)) lo = 1;
        }
        if (lw) atomicOr(&f_weird, 1);
        if (lo) atomicOr(&f_odd, 1);
        __syncthreads();
        if (t == 0) g_mask_mode = f_weird ? 2 : (f_odd ? 0 : 1);
    }
}

// ---------------------------------------------------------------------------
// GEMM: fp16 2-sweep (Ahi*B + Alo*B), M=32 x N=320 x K=768 per CTA,
// 296 CTAs x 256 threads, 2 CTAs/SM. Fused bias+LN+score epilogue.
// Warp w covers cols [w*40, w*40+40), all 32 rows.
// ---------------------------------------------------------------------------
__global__ __launch_bounds__(256, 2)
void gemm_kernel(const float* __restrict__ b_lin, const float* __restrict__ gamma,
                 const float* __restrict__ beta, const float* __restrict__ w_score,
                 const float* __restrict__ b_score, float* __restrict__ out) {
    extern __shared__ char smem[];
    const uint32_t sbase = smem_u32(smem);
    const int t = threadIdx.x;
    const int blk = blockIdx.x;
    const int w = t >> 5, lane = t & 31;
    const int nb0 = w * 40;

    float* tb = (float*)(smem + SM_TAB);
    for (int i = t; i < NPADB; i += 256) {
        tb[i]             = (i < OUTD) ? b_lin[i]   : 0.0f;
        tb[NPADB + i]     = (i < OUTD) ? gamma[i]   : 0.0f;
        tb[2 * NPADB + i] = (i < OUTD) ? beta[i]    : 0.0f;
        tb[3 * NPADB + i] = (i < OUTD) ? w_score[i] : 0.0f;
    }

    float acc[2][5][4];
    #pragma unroll
    for (int mf = 0; mf < 2; mf++)
        #pragma unroll
        for (int nf = 0; nf < 5; nf++)
            #pragma unroll
            for (int q = 0; q < 4; q++) acc[mf][nf][q] = 0.0f;

    const unsigned char* atile_hi = g_Ahi + (size_t)blk * NCHUNK * A_CHUNK_BYTES;
    const unsigned char* atile_lo = g_Alo + (size_t)blk * NCHUNK * A_CHUNK_BYTES;

    // issue chunk 0: A hi/lo = 256+256 units, B = 2560 units (16B each)
    {
        const uint32_t sb = sbase;
        {
            int idx = t;                       // 256 units each for Ahi/Alo
            int row = idx >> 3, u = idx & 7;
            uint32_t d = row * 128 + ((u ^ (row & 7)) << 4);
            cp16(sb + OFF_AHI + d, atile_hi + idx * 16);
            cp16(sb + OFF_ALO + d, atile_lo + idx * 16);
        }
        #pragma unroll
        for (int j = 0; j < 10; j++) {
            int idx = t + 256 * j;
            int row = idx >> 3, u = idx & 7;
            uint32_t d = row * 128 + ((u ^ (row & 7)) << 4);
            cp16(sb + OFF_BHI + d, g_Bhi + idx * 16);
        }
        asm volatile("cp.async.commit_group;" ::: "memory");
    }

    #pragma unroll 1
    for (int c = 0; c < NCHUNK; ++c) {
        if (c + 1 < NCHUNK) {
            const uint32_t sb2 = sbase + ((c + 1) & 1) * STAGE_BYTES;
            const unsigned char* ah = atile_hi + (size_t)(c + 1) * A_CHUNK_BYTES;
            const unsigned char* al = atile_lo + (size_t)(c + 1) * A_CHUNK_BYTES;
            const unsigned char* bh = g_Bhi + (size_t)(c + 1) * B_CHUNK_BYTES;
            {
                int idx = t;
                int row = idx >> 3, u = idx & 7;
                uint32_t d = row * 128 + ((u ^ (row & 7)) << 4);
                cp16(sb2 + OFF_AHI + d, ah + idx * 16);
                cp16(sb2 + OFF_ALO + d, al + idx * 16);
            }
            #pragma unroll
            for (int j = 0; j < 10; j++) {
                int idx = t + 256 * j;
                int row = idx >> 3, u = idx & 7;
                uint32_t d = row * 128 + ((u ^ (row & 7)) << 4);
                cp16(sb2 + OFF_BHI + d, bh + idx * 16);
            }
            asm volatile("cp.async.commit_group;" ::: "memory");
            asm volatile("cp.async.wait_group 1;" ::: "memory");
        } else {
            asm volatile("cp.async.wait_group 0;" ::: "memory");
        }
        __syncthreads();

        const uint32_t sb = sbase + (c & 1) * STAGE_BYTES;
        const int sub = lane >> 3, rin = lane & 7;
        #pragma unroll
        for (int ks = 0; ks < 4; ks++) {
            uint32_t ah[2][4], al[2][4];
            #pragma unroll
            for (int mf = 0; mf < 2; mf++) {
                int row = mf * 16 + rin + ((sub & 1) << 3);
                int u = ks * 2 + (sub >> 1);
                ldsm4(ah[mf], swz_addr(sb + OFF_AHI, row, u));
                ldsm4(al[mf], swz_addr(sb + OFF_ALO, row, u));
            }
            #pragma unroll
            for (int nf = 0; nf < 5; nf++) {
                int brow = nb0 + nf * 8 + rin;
                int bu = ks * 2 + (sub & 1);
                uint32_t bh[2];
                ldsm2(bh, swz_addr(sb + OFF_BHI, brow, bu));
                mma16816(acc[0][nf], ah[0], bh);
                mma16816(acc[1][nf], ah[1], bh);
                mma16816(acc[0][nf], al[0], bh);
                mma16816(acc[1][nf], al[1], bh);
            }
        }
        __syncthreads();
    }

    // ---- epilogue: bias + LayerNorm + h write + score ----
    float* red_sum  = (float*)(smem + SM_RED);   // [8][32]
    float* red_sq   = red_sum + 256;             // [8][32]
    float* red_sc   = red_sum + 512;             // [8][32]
    float* red_mean = red_sum + 768;             // [32]
    float* red_rstd = red_sum + 800;             // [32]

    float sum[4] = {0, 0, 0, 0}, sq[4] = {0, 0, 0, 0};
    #pragma unroll
    for (int mf = 0; mf < 2; mf++)
        #pragma unroll
        for (int nf = 0; nf < 5; nf++) {
            int c0 = nb0 + nf * 8 + 2 * (lane & 3);
            float v0 = acc[mf][nf][0] + tb[c0];
            float v1 = acc[mf][nf][1] + tb[c0 + 1];
            float v2 = acc[mf][nf][2] + tb[c0];
            float v3 = acc[mf][nf][3] + tb[c0 + 1];
            sum[mf * 2]     += v0 + v1;  sq[mf * 2]     += v0 * v0 + v1 * v1;
            sum[mf * 2 + 1] += v2 + v3;  sq[mf * 2 + 1] += v2 * v2 + v3 * v3;
        }
    #pragma unroll
    for (int ri = 0; ri < 4; ri++) {
        #pragma unroll
        for (int o = 1; o <= 2; o <<= 1) {
            sum[ri] += __shfl_xor_sync(0xffffffffu, sum[ri], o);
            sq[ri]  += __shfl_xor_sync(0xffffffffu, sq[ri], o);
        }
    }
    if ((lane & 3) == 0) {
        #pragma unroll
        for (int ri = 0; ri < 4; ri++) {
            int row = (ri >> 1) * 16 + (ri & 1) * 8 + (lane >> 2);
            red_sum[w * 32 + row] = sum[ri];
            red_sq[w * 32 + row]  = sq[ri];
        }
    }
    __syncthreads();
    if (t < TROWS) {
        float s = 0.0f, qv = 0.0f;
        #pragma unroll
        for (int j = 0; j < 8; j++) { s += red_sum[j * 32 + t]; qv += red_sq[j * 32 + t]; }
        float mean = s * (1.0f / OUTD);
        float var = qv * (1.0f / OUTD) - mean * mean;
        red_mean[t] = mean;
        red_rstd[t] = rsqrtf(fmaxf(var, 0.0f) + EPSV);
    }
    __syncthreads();

    const float* sg  = tb + NPADB;
    const float* sbe = tb + 2 * NPADB;
    const float* sw  = tb + 3 * NPADB;
    float sc[4] = {0, 0, 0, 0};
    #pragma unroll
    for (int mf = 0; mf < 2; mf++) {
        int row01 = mf * 16 + (lane >> 2);
        int row23 = row01 + 8;
        float m0 = red_mean[row01], r0 = red_rstd[row01];
        float m1 = red_mean[row23], r1 = red_rstd[row23];
        int g01 = blk * TROWS + row01;
        int g23 = blk * TROWS + row23;
        float* o01 = (blk < NBLK1T) ? out + (size_t)g01 * OUTD
                                    : out + HK_OFF + (size_t)(g01 - NSPAN1) * OUTD;
        float* o23 = (blk < NBLK1T) ? out + (size_t)g23 * OUTD
                                    : out + HK_OFF + (size_t)(g23 - NSPAN1) * OUTD;
        #pragma unroll
        for (int nf = 0; nf < 5; nf++) {
            int c0 = nb0 + nf * 8 + 2 * (lane & 3);
            float v0 = acc[mf][nf][0] + tb[c0];
            float v1 = acc[mf][nf][1] + tb[c0 + 1];
            float v2 = acc[mf][nf][2] + tb[c0];
            float v3 = acc[mf][nf][3] + tb[c0 + 1];
            float h0 = (v0 - m0) * r0 * sg[c0]     + sbe[c0];
            float h1 = (v1 - m0) * r0 * sg[c0 + 1] + sbe[c0 + 1];
            float h2 = (v2 - m1) * r1 * sg[c0]     + sbe[c0];
            float h3 = (v3 - m1) * r1 * sg[c0 + 1] + sbe[c0 + 1];
            sc[mf * 2]     += h0 * sw[c0] + h1 * sw[c0 + 1];
            sc[mf * 2 + 1] += h2 * sw[c0] + h3 * sw[c0 + 1];
            if (c0 < OUTD) {
                *(float2*)(o01 + c0) = make_float2(h0, h1);
                *(float2*)(o23 + c0) = make_float2(h2, h3);
            }
        }
    }
    #pragma unroll
    for (int ri = 0; ri < 4; ri++)
        #pragma unroll
        for (int o = 1; o <= 2; o <<= 1)
            sc[ri] += __shfl_xor_sync(0xffffffffu, sc[ri], o);
    if ((lane & 3) == 0) {
        #pragma unroll
        for (int ri = 0; ri < 4; ri++) {
            int row = (ri >> 1) * 16 + (ri & 1) * 8 + (lane >> 2);
            red_sc[w * 32 + row] = sc[ri];
        }
    }
    __syncthreads();
    if (t < TROWS) {
        float s = 0.0f;
        #pragma unroll
        for (int j = 0; j < 8; j++) s += red_sc[j * 32 + t];
        g_scores[blk * TROWS + t] = s + b_score[0];
    }
}

// ---------------------------------------------------------------------------
// fused softmax + broadcast
// ---------------------------------------------------------------------------
__global__ __launch_bounds__(256)
void softmax_bcast_kernel(const void* __restrict__ mask1,
                          const void* __restrict__ maskk,
                          float* __restrict__ out) {
    const int mode = g_mask_mode;
    const int t = threadIdx.x;
    if (blockIdx.x < NB) {
        const int b = blockIdx.x;
        __shared__ float red[4];
        __shared__ float sh[L1];
        float scv = 0.0f; bool msk = true;
        if (t < L1) {
            scv = g_scores[b * L1 + t];
            msk = read_mask(mask1, b * L1 + t, mode);
        }
        float val = (t < L1 && !msk) ? scv : -3.0e38f;
        float mx = val;
        #pragma unroll
        for (int o = 16; o; o >>= 1) mx = fmaxf(mx, __shfl_xor_sync(0xffffffffu, mx, o));
        if (t < L1 && (t & 31) == 0) red[t >> 5] = mx;
        __syncthreads();
        mx = fmaxf(fmaxf(red[0], red[1]), fmaxf(red[2], red[3]));
        __syncthreads();
        float ex = (t < L1 && !msk) ? expf(scv - mx) : 0.0f;
        float sm = ex;
        #pragma unroll
        for (int o = 16; o; o >>= 1) sm += __shfl_xor_sync(0xffffffffu, sm, o);
        if (t < L1 && (t & 31) == 0) red[t >> 5] = sm;
        __syncthreads();
        sm = red[0] + red[1] + red[2] + red[3];
        if (t < L1) sh[t] = ex / sm;
        __syncthreads();
        float4* o4 = (float4*)(out + SCORE_OFF + (size_t)b * L1 * OUTD);
        const int Q = OUTD / 4;            // 75
        for (int w2 = t; w2 < L1 * Q; w2 += 256) {
            int row = w2 / Q;
            float p = sh[row];
            o4[w2] = make_float4(p, p, p, p);
        }
    } else {
        const int b = blockIdx.x - NB;
        if (t < 32) {
            bool msk = true;
            float scv = 0.0f;
            if (t < KN) {
                msk = read_mask(maskk, b * KN + t, mode);
                scv = g_scores[NSPAN1 + b * KN + t];
            }
            float val = (t < KN && !msk) ? scv : -3.0e38f;
            float mx = val;
            #pragma unroll
            for (int o = 16; o; o >>= 1) mx = fmaxf(mx, __shfl_xor_sync(0xffffffffu, mx, o));
            float ex = (t < KN && !msk) ? expf(scv - mx) : 0.0f;
            float sm = ex;
            #pragma unroll
            for (int o = 16; o; o >>= 1) sm += __shfl_xor_sync(0xffffffffu, sm, o);
            if (t < KN) out[SK_OFF + b * KN + t] = ex / sm;
        }
    }
}

extern "C" void kernel_launch(void* const* d_in, const int* in_sizes, int n_in,
                              void* d_out, int out_size) {
    const float* t1    = (const float*)d_in[0];
    const float* know  = (const float*)d_in[1];
    const int*   s1s   = (const int*)d_in[2];
    const int*   s1e   = (const int*)d_in[3];
    const void*  mask1 = d_in[4];
    const int*   sks   = (const int*)d_in[5];
    const int*   ske   = (const int*)d_in[6];
    const void*  maskk = d_in[7];
    const float* W     = (const float*)d_in[8];
    const float* bl    = (const float*)d_in[9];
    const float* gm    = (const float*)d_in[10];
    const float* bt    = (const float*)d_in[11];
    const float* ws    = (const float*)d_in[12];
    const float* bs    = (const float*)d_in[13];
    float* out = (float*)d_out;

    cudaFuncSetAttribute(gemm_kernel, cudaFuncAttributeMaxDynamicSharedMemorySize,
                         SMEM_BYTES);
    prep_kernel<<<PREP_BLKS, 256>>>(t1, know, s1s, s1e, sks, ske, W,
                                    (const unsigned char*)mask1,
                                    (const unsigned char*)maskk);
    gemm_kernel<<<NTILES, 256, SMEM_BYTES>>>(bl, gm, bt, ws, bs, out);
    softmax_bcast_kernel<<<2 * NB, 256>>>(mask1, maskk, out);
}

// round 10
// speedup vs baseline: 1.6812x; 1.4643x over previous
#include <cuda_runtime.h>
#include <cuda_fp16.h>
#include <stdint.h>
#include <math.h>

#define NB   64
#define LSEQ 510
#define DDIM 768
#define L1   128
#define KN   20
#define OUTD 300
#define EPSV 1e-5f

#define NSPAN1 (NB * L1)          // 8192
#define NSPANK (NB * KN)          // 1280
#define NSPANS (NSPAN1 + NSPANK)  // 9472
#define TROWS  32
#define NTILES (NSPANS / TROWS)   // 296 = 2 CTAs x 148 SMs
#define NBLK1T (NSPAN1 / TROWS)   // 256

#define NCHUNK 12                 // K chunks of 64
#define NPADB  320

#define H1_OFF    0
#define SCORE_OFF (NB * L1 * OUTD)
#define HK_OFF    (2 * NB * L1 * OUTD)
#define SK_OFF    (HK_OFF + NB * KN * OUTD)

#define A_CHUNK_BYTES 4096         // 32 rows x 128B (fp16)
#define B_CHUNK_BYTES 40960        // 320 rows x 128B (fp16)

__device__ __align__(16) unsigned char g_Ahi[NTILES * NCHUNK * A_CHUNK_BYTES];
__device__ __align__(16) unsigned char g_Bhi[NCHUNK * B_CHUNK_BYTES];
__device__ float g_scores[NSPANS];
__device__ int   g_mask_mode;

// smem: per stage Ahi 4K | Bhi 40K = 44K; x2 stages; tables; reduction
#define STAGE_BYTES 45056
#define OFF_AHI 0
#define OFF_BHI 4096
#define SM_TAB  (2 * STAGE_BYTES)          // 90112
#define SM_RED  (SM_TAB + 5120)           // 95232
#define SMEM_BYTES (SM_RED + 3584)        // 98816 -> 2 CTAs/SM

static __device__ __forceinline__ uint32_t smem_u32(const void* p) {
    uint32_t a;
    asm("{ .reg .u64 t; cvta.to.shared.u64 t, %1; cvt.u32.u64 %0, t; }" : "=r"(a) : "l"(p));
    return a;
}
static __device__ __forceinline__ void cp16(uint32_t s, const void* g) {
    asm volatile("cp.async.cg.shared.global [%0], [%1], 16;" :: "r"(s), "l"(g) : "memory");
}
static __device__ __forceinline__ void ldsm4(uint32_t* r, uint32_t addr) {
    asm volatile("ldmatrix.sync.aligned.m8n8.x4.shared.b16 {%0,%1,%2,%3}, [%4];"
                 : "=r"(r[0]), "=r"(r[1]), "=r"(r[2]), "=r"(r[3]) : "r"(addr));
}
static __device__ __forceinline__ void ldsm2(uint32_t* r, uint32_t addr) {
    asm volatile("ldmatrix.sync.aligned.m8n8.x2.shared.b16 {%0,%1}, [%2];"
                 : "=r"(r[0]), "=r"(r[1]) : "r"(addr));
}
static __device__ __forceinline__ void mma16816(float* c, const uint32_t* a,
                                                const uint32_t* b) {
    asm volatile(
        "mma.sync.aligned.m16n8k16.row.col.f32.f16.f16.f32 "
        "{%0,%1,%2,%3}, {%4,%5,%6,%7}, {%8,%9}, {%0,%1,%2,%3};"
        : "+f"(c[0]), "+f"(c[1]), "+f"(c[2]), "+f"(c[3])
        : "r"(a[0]), "r"(a[1]), "r"(a[2]), "r"(a[3]), "r"(b[0]), "r"(b[1]));
}
static __device__ __forceinline__ uint32_t swz_addr(uint32_t base, int row, int u) {
    return base + row * 128 + ((u ^ (row & 7)) << 4);
}
static __device__ __forceinline__ bool read_mask(const void* m, int i, int mode) {
    if (mode == 0) return ((const unsigned char*)m)[i] != 0;
    if (mode == 1) return ((const int*)m)[i] != 0;
    return ((const float*)m)[i] != 0.0f;
}

// ---------------------------------------------------------------------------
// prep: blocks [0,1184): warp-per-span pool -> fp16;
//       blocks [1184,1304): W -> fp16; block 1304: mask detect.
// ---------------------------------------------------------------------------
#define PREP_SPAN_BLKS (NSPANS / 8)   // 1184
#define PREP_W_BLKS    120
#define PREP_BLKS      (PREP_SPAN_BLKS + PREP_W_BLKS + 1)

__global__ __launch_bounds__(256)
void prep_kernel(const float* __restrict__ t1, const float* __restrict__ know,
                 const int* __restrict__ s1s, const int* __restrict__ s1e,
                 const int* __restrict__ sks, const int* __restrict__ ske,
                 const float* __restrict__ W,
                 const unsigned char* __restrict__ mask1,
                 const unsigned char* __restrict__ maskk) {
    const int bid = blockIdx.x;
    const int t = threadIdx.x;
    if (bid < PREP_SPAN_BLKS) {
        const int w = t >> 5, lane = t & 31;
        const int rid = bid * 8 + w;
        const float* src; int b, s, e;
        if (rid < NSPAN1) { src = t1; b = rid >> 7; s = s1s[rid]; e = s1e[rid]; }
        else { int j = rid - NSPAN1; src = know; b = j / KN; s = sks[j]; e = ske[j]; }
        int len = e - s; if (len < 1) len = 1;
        const float inv = 1.0f / (float)len;
        const float* base = src + (size_t)(b * LSEQ + s) * DDIM + lane * 8;
        float v[24];
        #pragma unroll
        for (int j = 0; j < 24; j++) v[j] = 0.0f;
        for (int rr = 0; rr < len; rr++) {
            const float* rowp = base + (size_t)rr * DDIM;
            float4 f[6];
            #pragma unroll
            for (int g = 0; g < 3; g++) {
                f[2 * g]     = *(const float4*)(rowp + g * 256);
                f[2 * g + 1] = *(const float4*)(rowp + g * 256 + 4);
            }
            #pragma unroll
            for (int g = 0; g < 3; g++) {
                v[g*8+0] += f[2*g].x;   v[g*8+1] += f[2*g].y;
                v[g*8+2] += f[2*g].z;   v[g*8+3] += f[2*g].w;
                v[g*8+4] += f[2*g+1].x; v[g*8+5] += f[2*g+1].y;
                v[g*8+6] += f[2*g+1].z; v[g*8+7] += f[2*g+1].w;
            }
        }
        const int tile = rid >> 5, r = rid & 31;
        #pragma unroll
        for (int g = 0; g < 3; g++) {
            union { unsigned short u[8]; uint4 q; } ph;
            #pragma unroll
            for (int j = 0; j < 8; j++) {
                __half h = __float2half_rn(v[g * 8 + j] * inv);
                ph.u[j] = *(unsigned short*)&h;
            }
            const int idx8 = g * 32 + lane;
            const int chunk = idx8 >> 3, grp = idx8 & 7;
            size_t off = (size_t)(tile * NCHUNK + chunk) * A_CHUNK_BYTES
                       + r * 128 + grp * 16;
            *(uint4*)(g_Ahi + off) = ph.q;
        }
    } else if (bid < PREP_SPAN_BLKS + PREP_W_BLKS) {
        const int u = (bid - PREP_SPAN_BLKS) * 256 + t;   // [0, 30720)
        const int row = u / 96;
        const int idx8 = u - row * 96;
        const int c0 = idx8 * 8;
        union { unsigned short s[8]; uint4 q; } ph;
        if (row < OUTD) {
            const float4* p4 = (const float4*)(W + (size_t)row * DDIM + c0);
            float4 a = p4[0], bb = p4[1];
            float v[8] = {a.x, a.y, a.z, a.w, bb.x, bb.y, bb.z, bb.w};
            #pragma unroll
            for (int j = 0; j < 8; j++) {
                __half h = __float2half_rn(v[j]);
                ph.s[j] = *(unsigned short*)&h;
            }
        } else {
            ph.q = make_uint4(0, 0, 0, 0);
        }
        const int chunk = idx8 >> 3, grp = idx8 & 7;
        size_t off = (size_t)chunk * B_CHUNK_BYTES + row * 128 + grp * 16;
        *(uint4*)(g_Bhi + off) = ph.q;
    } else {
        __shared__ int f_weird, f_odd;
        if (t == 0) { f_weird = 0; f_odd = 0; }
        __syncthreads();
        int lw = 0, lo = 0;
        for (int i = t; i < NB * KN; i += 256) {
            unsigned char vv = maskk[i];
            if (vv > 1) lw = 1;
            if (vv && (i & 3)) lo = 1;
        }
        for (int i = t; i < NB * L1; i += 256) {
            unsigned char vv = mask1[i];
            if (vv > 1) lw = 1;
            if (vv && (i & 3)) lo = 1;
        }
        if (lw) atomicOr(&f_weird, 1);
        if (lo) atomicOr(&f_odd, 1);
        __syncthreads();
        if (t == 0) g_mask_mode = f_weird ? 2 : (f_odd ? 0 : 1);
    }
}

// ---------------------------------------------------------------------------
// GEMM: fp16 1-sweep, M=32 x N=320 x K=768 per CTA, 296 CTAs x 256 threads,
// 2 CTAs/SM. Warp w covers cols [w*40, w*40+40). Fused bias+LN+score epilogue.
// ---------------------------------------------------------------------------
__global__ __launch_bounds__(256, 2)
void gemm_kernel(const float* __restrict__ b_lin, const float* __restrict__ gamma,
                 const float* __restrict__ beta, const float* __restrict__ w_score,
                 const float* __restrict__ b_score, float* __restrict__ out) {
    extern __shared__ char smem[];
    const uint32_t sbase = smem_u32(smem);
    const int t = threadIdx.x;
    const int blk = blockIdx.x;
    const int w = t >> 5, lane = t & 31;
    const int nb0 = w * 40;

    float* tb = (float*)(smem + SM_TAB);
    for (int i = t; i < NPADB; i += 256) {
        tb[i]             = (i < OUTD) ? b_lin[i]   : 0.0f;
        tb[NPADB + i]     = (i < OUTD) ? gamma[i]   : 0.0f;
        tb[2 * NPADB + i] = (i < OUTD) ? beta[i]    : 0.0f;
        tb[3 * NPADB + i] = (i < OUTD) ? w_score[i] : 0.0f;
    }

    float acc[2][5][4];
    #pragma unroll
    for (int mf = 0; mf < 2; mf++)
        #pragma unroll
        for (int nf = 0; nf < 5; nf++)
            #pragma unroll
            for (int q = 0; q < 4; q++) acc[mf][nf][q] = 0.0f;

    const unsigned char* atile = g_Ahi + (size_t)blk * NCHUNK * A_CHUNK_BYTES;

    // issue chunk 0: A = 256 units, B = 2560 units (16B each)
    {
        const uint32_t sb = sbase;
        {
            int idx = t;
            int row = idx >> 3, u = idx & 7;
            uint32_t d = row * 128 + ((u ^ (row & 7)) << 4);
            cp16(sb + OFF_AHI + d, atile + idx * 16);
        }
        #pragma unroll
        for (int j = 0; j < 10; j++) {
            int idx = t + 256 * j;
            int row = idx >> 3, u = idx & 7;
            uint32_t d = row * 128 + ((u ^ (row & 7)) << 4);
            cp16(sb + OFF_BHI + d, g_Bhi + idx * 16);
        }
        asm volatile("cp.async.commit_group;" ::: "memory");
    }

    #pragma unroll 1
    for (int c = 0; c < NCHUNK; ++c) {
        if (c + 1 < NCHUNK) {
            const uint32_t sb2 = sbase + ((c + 1) & 1) * STAGE_BYTES;
            const unsigned char* ah = atile + (size_t)(c + 1) * A_CHUNK_BYTES;
            const unsigned char* bh = g_Bhi + (size_t)(c + 1) * B_CHUNK_BYTES;
            {
                int idx = t;
                int row = idx >> 3, u = idx & 7;
                uint32_t d = row * 128 + ((u ^ (row & 7)) << 4);
                cp16(sb2 + OFF_AHI + d, ah + idx * 16);
            }
            #pragma unroll
            for (int j = 0; j < 10; j++) {
                int idx = t + 256 * j;
                int row = idx >> 3, u = idx & 7;
                uint32_t d = row * 128 + ((u ^ (row & 7)) << 4);
                cp16(sb2 + OFF_BHI + d, bh + idx * 16);
            }
            asm volatile("cp.async.commit_group;" ::: "memory");
            asm volatile("cp.async.wait_group 1;" ::: "memory");
        } else {
            asm volatile("cp.async.wait_group 0;" ::: "memory");
        }
        __syncthreads();

        const uint32_t sb = sbase + (c & 1) * STAGE_BYTES;
        const int sub = lane >> 3, rin = lane & 7;
        #pragma unroll
        for (int ks = 0; ks < 4; ks++) {
            uint32_t ah[2][4];
            #pragma unroll
            for (int mf = 0; mf < 2; mf++) {
                int row = mf * 16 + rin + ((sub & 1) << 3);
                int u = ks * 2 + (sub >> 1);
                ldsm4(ah[mf], swz_addr(sb + OFF_AHI, row, u));
            }
            #pragma unroll
            for (int nf = 0; nf < 5; nf++) {
                int brow = nb0 + nf * 8 + rin;
                int bu = ks * 2 + (sub & 1);
                uint32_t bh[2];
                ldsm2(bh, swz_addr(sb + OFF_BHI, brow, bu));
                mma16816(acc[0][nf], ah[0], bh);
                mma16816(acc[1][nf], ah[1], bh);
            }
        }
        __syncthreads();
    }

    // ---- epilogue: bias + LayerNorm + h write + score ----
    float* red_sum  = (float*)(smem + SM_RED);   // [8][32]
    float* red_sq   = red_sum + 256;             // [8][32]
    float* red_sc   = red_sum + 512;             // [8][32]
    float* red_mean = red_sum + 768;             // [32]
    float* red_rstd = red_sum + 800;             // [32]

    float sum[4] = {0, 0, 0, 0}, sq[4] = {0, 0, 0, 0};
    #pragma unroll
    for (int mf = 0; mf < 2; mf++)
        #pragma unroll
        for (int nf = 0; nf < 5; nf++) {
            int c0 = nb0 + nf * 8 + 2 * (lane & 3);
            float v0 = acc[mf][nf][0] + tb[c0];
            float v1 = acc[mf][nf][1] + tb[c0 + 1];
            float v2 = acc[mf][nf][2] + tb[c0];
            float v3 = acc[mf][nf][3] + tb[c0 + 1];
            sum[mf * 2]     += v0 + v1;  sq[mf * 2]     += v0 * v0 + v1 * v1;
            sum[mf * 2 + 1] += v2 + v3;  sq[mf * 2 + 1] += v2 * v2 + v3 * v3;
        }
    #pragma unroll
    for (int ri = 0; ri < 4; ri++) {
        #pragma unroll
        for (int o = 1; o <= 2; o <<= 1) {
            sum[ri] += __shfl_xor_sync(0xffffffffu, sum[ri], o);
            sq[ri]  += __shfl_xor_sync(0xffffffffu, sq[ri], o);
        }
    }
    if ((lane & 3) == 0) {
        #pragma unroll
        for (int ri = 0; ri < 4; ri++) {
            int row = (ri >> 1) * 16 + (ri & 1) * 8 + (lane >> 2);
            red_sum[w * 32 + row] = sum[ri];
            red_sq[w * 32 + row]  = sq[ri];
        }
    }
    __syncthreads();
    if (t < TROWS) {
        float s = 0.0f, qv = 0.0f;
        #pragma unroll
        for (int j = 0; j < 8; j++) { s += red_sum[j * 32 + t]; qv += red_sq[j * 32 + t]; }
        float mean = s * (1.0f / OUTD);
        float var = qv * (1.0f / OUTD) - mean * mean;
        red_mean[t] = mean;
        red_rstd[t] = rsqrtf(fmaxf(var, 0.0f) + EPSV);
    }
    __syncthreads();

    const float* sg  = tb + NPADB;
    const float* sbe = tb + 2 * NPADB;
    const float* sw  = tb + 3 * NPADB;
    float sc[4] = {0, 0, 0, 0};
    #pragma unroll
    for (int mf = 0; mf < 2; mf++) {
        int row01 = mf * 16 + (lane >> 2);
        int row23 = row01 + 8;
        float m0 = red_mean[row01], r0 = red_rstd[row01];
        float m1 = red_mean[row23], r1 = red_rstd[row23];
        int g01 = blk * TROWS + row01;
        int g23 = blk * TROWS + row23;
        float* o01 = (blk < NBLK1T) ? out + (size_t)g01 * OUTD
                                    : out + HK_OFF + (size_t)(g01 - NSPAN1) * OUTD;
        float* o23 = (blk < NBLK1T) ? out + (size_t)g23 * OUTD
                                    : out + HK_OFF + (size_t)(g23 - NSPAN1) * OUTD;
        #pragma unroll
        for (int nf = 0; nf < 5; nf++) {
            int c0 = nb0 + nf * 8 + 2 * (lane & 3);
            float v0 = acc[mf][nf][0] + tb[c0];
            float v1 = acc[mf][nf][1] + tb[c0 + 1];
            float v2 = acc[mf][nf][2] + tb[c0];
            float v3 = acc[mf][nf][3] + tb[c0 + 1];
            float h0 = (v0 - m0) * r0 * sg[c0]     + sbe[c0];
            float h1 = (v1 - m0) * r0 * sg[c0 + 1] + sbe[c0 + 1];
            float h2 = (v2 - m1) * r1 * sg[c0]     + sbe[c0];
            float h3 = (v3 - m1) * r1 * sg[c0 + 1] + sbe[c0 + 1];
            sc[mf * 2]     += h0 * sw[c0] + h1 * sw[c0 + 1];
            sc[mf * 2 + 1] += h2 * sw[c0] + h3 * sw[c0 + 1];
            if (c0 < OUTD) {
                *(float2*)(o01 + c0) = make_float2(h0, h1);
                *(float2*)(o23 + c0) = make_float2(h2, h3);
            }
        }
    }
    #pragma unroll
    for (int ri = 0; ri < 4; ri++)
        #pragma unroll
        for (int o = 1; o <= 2; o <<= 1)
            sc[ri] += __shfl_xor_sync(0xffffffffu, sc[ri], o);
    if ((lane & 3) == 0) {
        #pragma unroll
        for (int ri = 0; ri < 4; ri++) {
            int row = (ri >> 1) * 16 + (ri & 1) * 8 + (lane >> 2);
            red_sc[w * 32 + row] = sc[ri];
        }
    }
    __syncthreads();
    if (t < TROWS) {
        float s = 0.0f;
        #pragma unroll
        for (int j = 0; j < 8; j++) s += red_sc[j * 32 + t];
        g_scores[blk * TROWS + t] = s + b_score[0];
    }
}

// ---------------------------------------------------------------------------
// softmax + broadcast: blocks 0..127 = (batch b = blk>>1, half = blk&1):
// redundantly compute softmax for b, write rows [half*64, half*64+64).
// Blocks 128..191: know softmax.
// ---------------------------------------------------------------------------
__global__ __launch_bounds__(256)
void softmax_bcast_kernel(const void* __restrict__ mask1,
                          const void* __restrict__ maskk,
                          float* __restrict__ out) {
    const int mode = g_mask_mode;
    const int t = threadIdx.x;
    if (blockIdx.x < 2 * NB) {
        const int b = blockIdx.x >> 1;
        const int half = blockIdx.x & 1;
        __shared__ float red[4];
        __shared__ float sh[L1];
        float scv = 0.0f; bool msk = true;
        if (t < L1) {
            scv = g_scores[b * L1 + t];
            msk = read_mask(mask1, b * L1 + t, mode);
        }
        float val = (t < L1 && !msk) ? scv : -3.0e38f;
        float mx = val;
        #pragma unroll
        for (int o = 16; o; o >>= 1) mx = fmaxf(mx, __shfl_xor_sync(0xffffffffu, mx, o));
        if (t < L1 && (t & 31) == 0) red[t >> 5] = mx;
        __syncthreads();
        mx = fmaxf(fmaxf(red[0], red[1]), fmaxf(red[2], red[3]));
        __syncthreads();
        float ex = (t < L1 && !msk) ? expf(scv - mx) : 0.0f;
        float sm = ex;
        #pragma unroll
        for (int o = 16; o; o >>= 1) sm += __shfl_xor_sync(0xffffffffu, sm, o);
        if (t < L1 && (t & 31) == 0) red[t >> 5] = sm;
        __syncthreads();
        sm = red[0] + red[1] + red[2] + red[3];
        if (t < L1) sh[t] = ex / sm;
        __syncthreads();
        float4* o4 = (float4*)(out + SCORE_OFF + (size_t)b * L1 * OUTD);
        const int Q = OUTD / 4;            // 75
        for (int w2 = t; w2 < 64 * Q; w2 += 256) {
            int row = half * 64 + w2 / Q;
            float p = sh[row];
            o4[row * Q + (w2 % Q)] = make_float4(p, p, p, p);
        }
    } else {
        const int b = blockIdx.x - 2 * NB;
        if (t < 32) {
            bool msk = true;
            float scv = 0.0f;
            if (t < KN) {
                msk = read_mask(maskk, b * KN + t, mode);
                scv = g_scores[NSPAN1 + b * KN + t];
            }
            float val = (t < KN && !msk) ? scv : -3.0e38f;
            float mx = val;
            #pragma unroll
            for (int o = 16; o; o >>= 1) mx = fmaxf(mx, __shfl_xor_sync(0xffffffffu, mx, o));
            float ex = (t < KN && !msk) ? expf(scv - mx) : 0.0f;
            float sm = ex;
            #pragma unroll
            for (int o = 16; o; o >>= 1) sm += __shfl_xor_sync(0xffffffffu, sm, o);
            if (t < KN) out[SK_OFF + b * KN + t] = ex / sm;
        }
    }
}

extern "C" void kernel_launch(void* const* d_in, const int* in_sizes, int n_in,
                              void* d_out, int out_size) {
    const float* t1    = (const float*)d_in[0];
    const float* know  = (const float*)d_in[1];
    const int*   s1s   = (const int*)d_in[2];
    const int*   s1e   = (const int*)d_in[3];
    const void*  mask1 = d_in[4];
    const int*   sks   = (const int*)d_in[5];
    const int*   ske   = (const int*)d_in[6];
    const void*  maskk = d_in[7];
    const float* W     = (const float*)d_in[8];
    const float* bl    = (const float*)d_in[9];
    const float* gm    = (const float*)d_in[10];
    const float* bt    = (const float*)d_in[11];
    const float* ws    = (const float*)d_in[12];
    const float* bs    = (const float*)d_in[13];
    float* out = (float*)d_out;

    cudaFuncSetAttribute(gemm_kernel, cudaFuncAttributeMaxDynamicSharedMemorySize,
                         SMEM_BYTES);
    prep_kernel<<<PREP_BLKS, 256>>>(t1, know, s1s, s1e, sks, ske, W,
                                    (const unsigned char*)mask1,
                                    (const unsigned char*)maskk);
    gemm_kernel<<<NTILES, 256, SMEM_BYTES>>>(bl, gm, bt, ws, bs, out);
    softmax_bcast_kernel<<<3 * NB, 256>>>(mask1, maskk, out);
}